// round 7
// baseline (speedup 1.0000x reference)
#include <cuda_runtime.h>
#include <math.h>
#include <cstdint>

#define BATCH 2
#define TSEQ  2048
#define CDIM  1024
#define NHEAD 16
#define HDIM  64
#define MROWS (BATCH*TSEQ)          // 4096
#define QKV_N (3*CDIM)              // 3072

// Scratch (no runtime allocation allowed)
__device__ float g_qkv[MROWS * QKV_N];     // [B*T, 3C]  (tf32-rounded)
__device__ float g_y  [MROWS * CDIM];      // [B*T, C]   (tf32-rounded)
__device__ float g_x  [MROWS * CDIM];      // tf32-rounded copy of x
__device__ float g_wt_qkv[QKV_N * CDIM];   // W_qkv^T  (tf32-rounded)
__device__ float g_wt_o  [CDIM * CDIM];    // W_o^T    (tf32-rounded)

// ---------------------------------------------------------------------------
// helpers
// ---------------------------------------------------------------------------
__device__ __forceinline__ uint32_t smem_u32(const void* p) {
    uint32_t a;
    asm("{ .reg .u64 t; cvta.to.shared.u64 t, %1; cvt.u32.u64 %0, t; }" : "=r"(a) : "l"(p));
    return a;
}
__device__ __forceinline__ uint32_t f2tf(float f) {
    uint32_t u;
    asm("cvt.rna.tf32.f32 %0, %1;" : "=r"(u) : "f"(f));
    return u;
}
__device__ __forceinline__ float f2tf_f(float f) { return __uint_as_float(f2tf(f)); }

#define CP_ASYNC16(dst, src) \
    asm volatile("cp.async.cg.shared.global [%0], [%1], 16;" :: "r"(dst), "l"(src) : "memory")
#define CP_COMMIT() asm volatile("cp.async.commit_group;" ::: "memory")
#define CP_WAIT(n)  asm volatile("cp.async.wait_group %0;" :: "n"(n) : "memory")

__device__ __forceinline__ void mma_tf32(float* c, const uint32_t* a, const uint32_t* b) {
    asm volatile(
        "mma.sync.aligned.m16n8k8.row.col.f32.tf32.tf32.f32 "
        "{%0,%1,%2,%3}, {%4,%5,%6,%7}, {%8,%9}, {%0,%1,%2,%3};"
        : "+f"(c[0]), "+f"(c[1]), "+f"(c[2]), "+f"(c[3])
        : "r"(a[0]), "r"(a[1]), "r"(a[2]), "r"(a[3]), "r"(b[0]), "r"(b[1]));
}

// ---------------------------------------------------------------------------
// mma.sync tf32 GEMM: C[M,N] = A[M,K] @ Bt[N,K]^T + bias[N]
// Inputs pre-rounded to tf32. k-permuted fragments: all LDS are 64-bit.
// CTA 128x256, BK=32, 3-stage cp.async. 512 threads = 16 warps (2x8),
// warp tile 64x32 -> 64 accum regs/thread, 16 resident warps.
// ---------------------------------------------------------------------------
#define BM 128
#define BN 256
#define BK 32
#define NST 3
#define SROW 40                                  // == 8 mod 32: conflict-free LDS.64
#define STAGE_FLTS ((BM + BN) * SROW)            // 15360
#define GEMM_SMEM  (NST * STAGE_FLTS * 4)        // 184320 bytes
#define GTHREADS 512

template <bool ROUND>
__global__ __launch_bounds__(GTHREADS, 1) void gemm_mma(
    const float* __restrict__ A, const float* __restrict__ Bt,
    const float* __restrict__ bias, float* __restrict__ C,
    int M, int N, int K)
{
    extern __shared__ float sm[];
    const uint32_t sbase = smem_u32(sm);
    const int tid  = threadIdx.x;
    const int lane = tid & 31;
    const int w    = tid >> 5;
    const int wr   = w >> 3;       // 0..1 (row block of 64)
    const int wc   = w & 7;        // 0..7 (col block of 32)
    const int g    = lane >> 2;
    const int la3  = lane & 3;
    const int row0 = blockIdx.y * BM;
    const int col0 = blockIdx.x * BN;

    float c[4][4][4];
    #pragma unroll
    for (int i = 0; i < 4; ++i)
        #pragma unroll
        for (int j = 0; j < 4; ++j)
            #pragma unroll
            for (int q = 0; q < 4; ++q) c[i][j][q] = 0.f;

    const int nchunk = K / BK;

    auto load_stage = [&](int s, int kt) {
        uint32_t sa = sbase + (uint32_t)(s * STAGE_FLTS) * 4u;
        uint32_t sb = sa + (uint32_t)(BM * SROW) * 4u;
        const float* Ab = A  + (size_t)row0 * K + kt * BK;
        const float* Bb = Bt + (size_t)col0 * K + kt * BK;
        #pragma unroll
        for (int it = 0; it < 2; ++it) {             // A: 128 rows x 8 chunks
            int idx = it * GTHREADS + tid;
            int r   = idx >> 3;
            int c4  = (idx & 7) * 4;
            CP_ASYNC16(sa + (uint32_t)(r * SROW + c4) * 4u, Ab + (size_t)r * K + c4);
        }
        #pragma unroll
        for (int it = 0; it < 4; ++it) {             // B: 256 rows x 8 chunks
            int idx = it * GTHREADS + tid;
            int r   = idx >> 3;
            int c4  = (idx & 7) * 4;
            CP_ASYNC16(sb + (uint32_t)(r * SROW + c4) * 4u, Bb + (size_t)r * K + c4);
        }
    };

    load_stage(0, 0); CP_COMMIT();
    load_stage(1, 1); CP_COMMIT();

    for (int kt = 0; kt < nchunk; ++kt) {
        CP_WAIT(1);
        __syncthreads();
        if (kt + 2 < nchunk) load_stage((kt + 2) % NST, kt + 2);
        CP_COMMIT();

        const float* sa = sm + (kt % NST) * STAGE_FLTS;
        const float* sb = sa + BM * SROW;
        #pragma unroll
        for (int ks = 0; ks < 4; ++ks) {
            const int kb = ks * 8 + 2 * la3;     // k-permuted pair base
            uint32_t af[4][4], bf[4][2];
            #pragma unroll
            for (int mt = 0; mt < 4; ++mt) {
                int r0 = wr * 64 + mt * 16 + g;
                float2 a02 = *(const float2*)&sa[r0 * SROW + kb];
                float2 a13 = *(const float2*)&sa[(r0 + 8) * SROW + kb];
                af[mt][0] = __float_as_uint(a02.x);
                af[mt][2] = __float_as_uint(a02.y);
                af[mt][1] = __float_as_uint(a13.x);
                af[mt][3] = __float_as_uint(a13.y);
            }
            #pragma unroll
            for (int nt = 0; nt < 4; ++nt) {
                int n0 = wc * 32 + nt * 8 + g;
                float2 b01 = *(const float2*)&sb[n0 * SROW + kb];
                bf[nt][0] = __float_as_uint(b01.x);
                bf[nt][1] = __float_as_uint(b01.y);
            }
            #pragma unroll
            for (int mt = 0; mt < 4; ++mt)
                #pragma unroll
                for (int nt = 0; nt < 4; ++nt)
                    mma_tf32(c[mt][nt], af[mt], bf[nt]);
        }
    }

    #pragma unroll
    for (int mt = 0; mt < 4; ++mt) {
        #pragma unroll
        for (int nt = 0; nt < 4; ++nt) {
            int r   = row0 + wr * 64 + mt * 16 + g;
            int col = col0 + wc * 32 + nt * 8 + la3 * 2;
            float2 bv = *(const float2*)&bias[col];
            float v00 = c[mt][nt][0] + bv.x, v01 = c[mt][nt][1] + bv.y;
            float v10 = c[mt][nt][2] + bv.x, v11 = c[mt][nt][3] + bv.y;
            if (ROUND) {
                v00 = f2tf_f(v00); v01 = f2tf_f(v01);
                v10 = f2tf_f(v10); v11 = f2tf_f(v11);
            }
            *(float2*)&C[(size_t)r * N + col]       = make_float2(v00, v01);
            *(float2*)&C[(size_t)(r + 8) * N + col] = make_float2(v10, v11);
        }
    }
}

// ---------------------------------------------------------------------------
// Weight transpose + tf32 round
// ---------------------------------------------------------------------------
__global__ __launch_bounds__(256) void transpose_k(
    const float* __restrict__ in, float* __restrict__ out, int R, int Ccols)
{
    __shared__ float t[32][33];
    int r0 = blockIdx.y * 32, c0 = blockIdx.x * 32;
    #pragma unroll
    for (int i = threadIdx.y; i < 32; i += 8)
        t[i][threadIdx.x] = in[(size_t)(r0 + i) * Ccols + c0 + threadIdx.x];
    __syncthreads();
    #pragma unroll
    for (int i = threadIdx.y; i < 32; i += 8)
        out[(size_t)(c0 + i) * R + r0 + threadIdx.x] = f2tf_f(t[threadIdx.x][i]);
}

__global__ __launch_bounds__(256) void round_x(
    const float* __restrict__ in, float* __restrict__ out)
{
    int i = (blockIdx.x * 256 + threadIdx.x) * 4;
    float4 v = *(const float4*)&in[i];
    v.x = f2tf_f(v.x); v.y = f2tf_f(v.y); v.z = f2tf_f(v.z); v.w = f2tf_f(v.w);
    *(float4*)&out[i] = v;
}

// ---------------------------------------------------------------------------
// Flash attention (causal), mma.sync tf32, k-permuted fragments.
// 128 queries x (b,h); 8 warps x 16 rows; KV tiles of 64, double-buffered.
// VT aliased into dead Q staging region; 108.5KB smem -> 2 CTAs/SM.
// ---------------------------------------------------------------------------
#define AQ 128
#define AKV 64
#define ASTR 72                                 // == 8 mod 32: conflict-free LDS.64
#define VSTG 68                                 // == 4 mod 32: conflict-free LDS.128
#define SM_QS 0
#define SM_VT 0                                 // alias: VT reuses Q staging
#define SM_KS (AQ * ASTR)                       // 9216
#define SM_VST (SM_KS + 2 * AKV * ASTR)         // 18432
#define ATTN_SMEM ((SM_VST + 2 * AKV * VSTG) * 4)   // 108544 bytes

__global__ __launch_bounds__(256, 2) void attn_mma(
    const float* __restrict__ qkv, float* __restrict__ y)
{
    extern __shared__ float sm[];
    const uint32_t sb = smem_u32(sm);
    const int tid  = threadIdx.x;
    const int lane = tid & 31;
    const int w    = tid >> 5;
    const int g    = lane >> 2;
    const int la3  = lane & 3;

    const int qblk = (gridDim.x - 1) - blockIdx.x;   // heavy blocks first
    const int q0   = qblk * AQ;
    const int h    = blockIdx.y;
    const int b    = blockIdx.z;
    const size_t base = (size_t)b * TSEQ * QKV_N + h * HDIM;

    // Load Q tile (scaled by 1/8, exact on tf32 values)
    for (int i = tid; i < AQ * 16; i += 256) {
        int r = i >> 4, c = (i & 15) * 4;
        float4 v = *(const float4*)&qkv[base + (size_t)(q0 + r) * QKV_N + c];
        v.x *= 0.125f; v.y *= 0.125f; v.z *= 0.125f; v.w *= 0.125f;
        *(float4*)&sm[SM_QS + r * ASTR + c] = v;
    }

    const int ntile = q0 / AKV + 2;

    auto load_kv = [&](int t, int stage) {
        uint32_t ks_ = sb + (uint32_t)(SM_KS + stage * AKV * ASTR) * 4u;
        uint32_t vs_ = sb + (uint32_t)(SM_VST + stage * AKV * VSTG) * 4u;
        const float* Kg = qkv + base + CDIM     + (size_t)t * AKV * QKV_N;
        const float* Vg = qkv + base + 2 * CDIM + (size_t)t * AKV * QKV_N;
        #pragma unroll
        for (int it = 0; it < 4; ++it) {
            int idx = it * 256 + tid;
            int r = idx >> 4;               // key 0..63
            int c = (idx & 15) * 4;
            CP_ASYNC16(ks_ + (uint32_t)(r * ASTR + c) * 4u, Kg + (size_t)r * QKV_N + c);
            CP_ASYNC16(vs_ + (uint32_t)(r * VSTG + c) * 4u, Vg + (size_t)r * QKV_N + c);
        }
    };

    load_kv(0, 0); CP_COMMIT();
    __syncthreads();    // Qs visible

    // Q fragments (k-permuted): float2 loads, persistent in registers.
    uint32_t qf[8][4];
    const int rl1 = w * 16 + g;
    #pragma unroll
    for (int ks = 0; ks < 8; ++ks) {
        float2 q02 = *(const float2*)&sm[SM_QS + rl1 * ASTR + ks * 8 + 2 * la3];
        float2 q13 = *(const float2*)&sm[SM_QS + (rl1 + 8) * ASTR + ks * 8 + 2 * la3];
        qf[ks][0] = __float_as_uint(q02.x);
        qf[ks][2] = __float_as_uint(q02.y);
        qf[ks][1] = __float_as_uint(q13.x);
        qf[ks][3] = __float_as_uint(q13.y);
    }

    float o[8][4];
    #pragma unroll
    for (int nt = 0; nt < 8; ++nt)
        #pragma unroll
        for (int q = 0; q < 4; ++q) o[nt][q] = 0.f;
    float m0 = -1e30f, m1 = -1e30f, l0 = 0.f, l1 = 0.f;

    const int row1 = q0 + rl1;
    const int row2 = row1 + 8;

    for (int t = 0; t < ntile; ++t) {
        if (t + 1 < ntile) load_kv(t + 1, (t + 1) & 1);
        CP_COMMIT();
        CP_WAIT(1);
        __syncthreads();   // KV(t) ready; prior PV reads of VT complete

        const int par = t & 1;
        const float* Ks_  = &sm[SM_KS  + par * AKV * ASTR];
        const float* Vst_ = &sm[SM_VST + par * AKV * VSTG];
        float*       Vt_  = &sm[SM_VT];

        // Transpose V stage -> VT [dim][key] (visible after next sync)
        #pragma unroll
        for (int it = 0; it < 4; ++it) {
            int idx = it * 256 + tid;
            int key = idx & 63;
            int c4  = (idx >> 6) * 4;
            float4 v = *(const float4*)&Vst_[key * VSTG + c4];
            Vt_[(c4 + 0) * ASTR + key] = v.x;
            Vt_[(c4 + 1) * ASTR + key] = v.y;
            Vt_[(c4 + 2) * ASTR + key] = v.z;
            Vt_[(c4 + 3) * ASTR + key] = v.w;
        }

        // S = Q K^T
        float s[8][4];
        #pragma unroll
        for (int nt = 0; nt < 8; ++nt)
            #pragma unroll
            for (int q = 0; q < 4; ++q) s[nt][q] = 0.f;
        #pragma unroll
        for (int ks = 0; ks < 8; ++ks) {
            #pragma unroll
            for (int nt = 0; nt < 8; ++nt) {
                float2 kk = *(const float2*)&Ks_[(nt * 8 + g) * ASTR + ks * 8 + 2 * la3];
                uint32_t bf[2] = { __float_as_uint(kk.x), __float_as_uint(kk.y) };
                mma_tf32(s[nt], qf[ks], bf);
            }
        }

        const int j0 = t * AKV;
        if (j0 >= q0) {   // diagonal region: causal mask
            #pragma unroll
            for (int nt = 0; nt < 8; ++nt) {
                int col = j0 + nt * 8 + 2 * la3;
                if (col     > row1) s[nt][0] = -1e30f;
                if (col + 1 > row1) s[nt][1] = -1e30f;
                if (col     > row2) s[nt][2] = -1e30f;
                if (col + 1 > row2) s[nt][3] = -1e30f;
            }
        }

        // row max
        float mx0 = -1e30f, mx1 = -1e30f;
        #pragma unroll
        for (int nt = 0; nt < 8; ++nt) {
            mx0 = fmaxf(mx0, fmaxf(s[nt][0], s[nt][1]));
            mx1 = fmaxf(mx1, fmaxf(s[nt][2], s[nt][3]));
        }
        mx0 = fmaxf(mx0, __shfl_xor_sync(0xffffffffu, mx0, 1));
        mx0 = fmaxf(mx0, __shfl_xor_sync(0xffffffffu, mx0, 2));
        mx1 = fmaxf(mx1, __shfl_xor_sync(0xffffffffu, mx1, 1));
        mx1 = fmaxf(mx1, __shfl_xor_sync(0xffffffffu, mx1, 2));

        float M0 = fmaxf(m0, mx0), M1 = fmaxf(m1, mx1);
        float corr0 = __expf(m0 - M0), corr1 = __expf(m1 - M1);
        m0 = M0; m1 = M1;

        #pragma unroll
        for (int nt = 0; nt < 8; ++nt) {
            o[nt][0] *= corr0; o[nt][1] *= corr0;
            o[nt][2] *= corr1; o[nt][3] *= corr1;
        }

        // P = exp(S - M) (tf32) IN-PLACE in s, permuted to PV A-frag layout
        float ps0 = 0.f, ps1 = 0.f;
        #pragma unroll
        for (int ks = 0; ks < 8; ++ks) {
            float p0 = f2tf_f(__expf(s[ks][0] - M0));
            float p1 = f2tf_f(__expf(s[ks][1] - M0));
            float p2 = f2tf_f(__expf(s[ks][2] - M1));
            float p3 = f2tf_f(__expf(s[ks][3] - M1));
            ps0 += p0 + p1;
            ps1 += p2 + p3;
            s[ks][0] = p0;      // (row g,   k=2*la3)
            s[ks][1] = p2;      // (row g+8, k=2*la3)
            s[ks][2] = p1;      // (row g,   k=2*la3+1)
            s[ks][3] = p3;      // (row g+8, k=2*la3+1)
        }

        ps0 += __shfl_xor_sync(0xffffffffu, ps0, 1);
        ps0 += __shfl_xor_sync(0xffffffffu, ps0, 2);
        ps1 += __shfl_xor_sync(0xffffffffu, ps1, 1);
        ps1 += __shfl_xor_sync(0xffffffffu, ps1, 2);
        l0 = l0 * corr0 + ps0;
        l1 = l1 * corr1 + ps1;

        __syncthreads();   // VT complete; all warps past K reads

        // O += P V
        #pragma unroll
        for (int ks = 0; ks < 8; ++ks) {
            #pragma unroll
            for (int nt = 0; nt < 8; ++nt) {
                float2 vv = *(const float2*)&Vt_[(nt * 8 + g) * ASTR + ks * 8 + 2 * la3];
                uint32_t bf[2] = { __float_as_uint(vv.x), __float_as_uint(vv.y) };
                mma_tf32(o[nt], (const uint32_t*)s[ks], bf);
            }
        }
    }

    const float inv0 = 1.f / l0, inv1 = 1.f / l1;
    float* y1 = &y[((size_t)b * TSEQ + row1) * CDIM + h * HDIM];
    float* y2 = &y[((size_t)b * TSEQ + row2) * CDIM + h * HDIM];
    #pragma unroll
    for (int nt = 0; nt < 8; ++nt) {
        int col = nt * 8 + 2 * la3;
        *(float2*)&y1[col] = make_float2(f2tf_f(o[nt][0] * inv0), f2tf_f(o[nt][1] * inv0));
        *(float2*)&y2[col] = make_float2(f2tf_f(o[nt][2] * inv1), f2tf_f(o[nt][3] * inv1));
    }
}

// ---------------------------------------------------------------------------
extern "C" void kernel_launch(void* const* d_in, const int* in_sizes, int n_in,
                              void* d_out, int out_size)
{
    const float* x     = (const float*)d_in[0];
    const float* W_qkv = (const float*)d_in[1];
    const float* b_qkv = (const float*)d_in[2];
    const float* W_o   = (const float*)d_in[3];
    const float* b_o   = (const float*)d_in[4];
    float* out = (float*)d_out;

    float *qkv_ptr, *y_ptr, *x_ptr, *wtq_ptr, *wto_ptr;
    cudaGetSymbolAddress((void**)&qkv_ptr, g_qkv);
    cudaGetSymbolAddress((void**)&y_ptr,   g_y);
    cudaGetSymbolAddress((void**)&x_ptr,   g_x);
    cudaGetSymbolAddress((void**)&wtq_ptr, g_wt_qkv);
    cudaGetSymbolAddress((void**)&wto_ptr, g_wt_o);

    cudaFuncSetAttribute(gemm_mma<true>,  cudaFuncAttributeMaxDynamicSharedMemorySize, GEMM_SMEM);
    cudaFuncSetAttribute(gemm_mma<false>, cudaFuncAttributeMaxDynamicSharedMemorySize, GEMM_SMEM);
    cudaFuncSetAttribute(attn_mma, cudaFuncAttributeMaxDynamicSharedMemorySize, ATTN_SMEM);

    // Pre-round inputs to tf32
    round_x<<<MROWS * CDIM / 1024, 256>>>(x, x_ptr);
    transpose_k<<<dim3(QKV_N / 32, CDIM / 32), dim3(32, 8)>>>(W_qkv, wtq_ptr, CDIM, QKV_N);
    transpose_k<<<dim3(CDIM / 32, CDIM / 32), dim3(32, 8)>>>(W_o, wto_ptr, CDIM, CDIM);

    // qkv = tf32_round(x @ W_qkv + b_qkv)   [4096, 3072]
    gemm_mma<true><<<dim3(QKV_N / BN, MROWS / BM), GTHREADS, GEMM_SMEM>>>(
        x_ptr, wtq_ptr, b_qkv, qkv_ptr, MROWS, QKV_N, CDIM);

    // y = attention(qkv)
    attn_mma<<<dim3(TSEQ / AQ, NHEAD, BATCH), 256, ATTN_SMEM>>>(qkv_ptr, y_ptr);

    // out = y @ W_o + b_o       [4096, 1024]
    gemm_mma<false><<<dim3(CDIM / BN, MROWS / BM), GTHREADS, GEMM_SMEM>>>(
        y_ptr, wto_ptr, b_o, out, MROWS, CDIM, CDIM);
}

// round 9
// speedup vs baseline: 1.0603x; 1.0603x over previous
#include <cuda_runtime.h>
#include <cuda_fp16.h>
#include <math.h>
#include <cstdint>

#define BATCH 2
#define TSEQ  2048
#define CDIM  1024
#define NHEAD 16
#define HDIM  64
#define MROWS (BATCH*TSEQ)          // 4096
#define QKV_N (3*CDIM)              // 3072

// Scratch (no runtime allocation allowed)
__device__ __half g_qkvh[MROWS * QKV_N];    // [B*T, 3C] half
__device__ __half g_yh  [MROWS * CDIM];     // [B*T, C]  half (attn out)
__device__ __half g_xh  [MROWS * CDIM];     // half copy of x
__device__ __half g_wtq [QKV_N * CDIM];     // W_qkv^T half
__device__ __half g_wto [CDIM * CDIM];      // W_o^T   half

// ---------------------------------------------------------------------------
// helpers
// ---------------------------------------------------------------------------
__device__ __forceinline__ uint32_t smem_u32(const void* p) {
    uint32_t a;
    asm("{ .reg .u64 t; cvta.to.shared.u64 t, %1; cvt.u32.u64 %0, t; }" : "=r"(a) : "l"(p));
    return a;
}
#define CP_ASYNC16(dst, src) \
    asm volatile("cp.async.cg.shared.global [%0], [%1], 16;" :: "r"(dst), "l"(src) : "memory")
#define CP_COMMIT() asm volatile("cp.async.commit_group;" ::: "memory")
#define CP_WAIT(n)  asm volatile("cp.async.wait_group %0;" :: "n"(n) : "memory")

__device__ __forceinline__ void ldsm4(uint32_t* r, uint32_t a) {
    asm volatile("ldmatrix.sync.aligned.m8n8.x4.shared.b16 {%0,%1,%2,%3}, [%4];"
        : "=r"(r[0]), "=r"(r[1]), "=r"(r[2]), "=r"(r[3]) : "r"(a));
}
__device__ __forceinline__ void ldsm4t(uint32_t* r, uint32_t a) {
    asm volatile("ldmatrix.sync.aligned.m8n8.x4.trans.shared.b16 {%0,%1,%2,%3}, [%4];"
        : "=r"(r[0]), "=r"(r[1]), "=r"(r[2]), "=r"(r[3]) : "r"(a));
}
__device__ __forceinline__ void mma_f16(float* c, const uint32_t* a, const uint32_t* b) {
    asm volatile(
        "mma.sync.aligned.m16n8k16.row.col.f32.f16.f16.f32 "
        "{%0,%1,%2,%3}, {%4,%5,%6,%7}, {%8,%9}, {%0,%1,%2,%3};"
        : "+f"(c[0]), "+f"(c[1]), "+f"(c[2]), "+f"(c[3])
        : "r"(a[0]), "r"(a[1]), "r"(a[2]), "r"(a[3]), "r"(b[0]), "r"(b[1]));
}

// ---------------------------------------------------------------------------
// fp16 GEMM: C[M,N] = A[M,K] @ Bt[N,K]^T + bias[N]
// CTA 128x256, BK=32, 3-stage cp.async, 512 threads (16 warps, 2x8),
// warp tile 64x32. All fragment loads via ldmatrix.x4.
// ---------------------------------------------------------------------------
#define BM 128
#define BN 256
#define BK 32
#define NST 3
#define SROWH 40                                 // halves; 80B: conflict-free ldmatrix
#define STAGE_H ((BM + BN) * SROWH)              // 15360 halves
#define GEMM_SMEM (NST * STAGE_H * 2)            // 92160 bytes
#define GTHREADS 512

template <bool HOUT>
__global__ __launch_bounds__(GTHREADS, 1) void gemm_h(
    const __half* __restrict__ A, const __half* __restrict__ Bt,
    const float* __restrict__ bias, void* __restrict__ Cv,
    int M, int N, int K)
{
    extern __shared__ __half smh[];
    const uint32_t sbase = smem_u32(smh);
    const int tid  = threadIdx.x;
    const int lane = tid & 31;
    const int w    = tid >> 5;
    const int wr   = w >> 3;       // 0..1
    const int wc   = w & 7;        // 0..7
    const int g    = lane >> 2;
    const int la3  = lane & 3;
    const int m4   = lane >> 3;    // ldmatrix matrix id
    const int ri   = lane & 7;     // ldmatrix row-in-matrix
    const int row0 = blockIdx.y * BM;
    const int col0 = blockIdx.x * BN;

    float c[4][4][4];
    #pragma unroll
    for (int i = 0; i < 4; ++i)
        #pragma unroll
        for (int j = 0; j < 4; ++j)
            #pragma unroll
            for (int q = 0; q < 4; ++q) c[i][j][q] = 0.f;

    const int nchunk = K / BK;

    auto load_stage = [&](int s, int kt) {
        uint32_t sa = sbase + (uint32_t)(s * STAGE_H) * 2u;
        uint32_t sb = sa + (uint32_t)(BM * SROWH) * 2u;
        const __half* Ab = A  + (size_t)row0 * K + kt * BK;
        const __half* Bb = Bt + (size_t)col0 * K + kt * BK;
        {   // A: 128 rows x 4 chunks of 8 halves = 512
            int r = tid >> 2, ch = (tid & 3) * 8;
            CP_ASYNC16(sa + (uint32_t)(r * SROWH + ch) * 2u, Ab + (size_t)r * K + ch);
        }
        #pragma unroll
        for (int it = 0; it < 2; ++it) {   // B: 256 rows x 4 chunks = 1024
            int idx = it * GTHREADS + tid;
            int r = idx >> 2, ch = (idx & 3) * 8;
            CP_ASYNC16(sb + (uint32_t)(r * SROWH + ch) * 2u, Bb + (size_t)r * K + ch);
        }
    };

    load_stage(0, 0); CP_COMMIT();
    load_stage(1, 1); CP_COMMIT();

    for (int kt = 0; kt < nchunk; ++kt) {
        CP_WAIT(1);
        __syncthreads();
        if (kt + 2 < nchunk) load_stage((kt + 2) % NST, kt + 2);
        CP_COMMIT();

        uint32_t sa = sbase + (uint32_t)((kt % NST) * STAGE_H) * 2u;
        uint32_t sb = sa + (uint32_t)(BM * SROWH) * 2u;
        #pragma unroll
        for (int ks = 0; ks < 2; ++ks) {       // k-steps of 16
            uint32_t af[4][4], bf[4][2];
            #pragma unroll
            for (int mt = 0; mt < 4; ++mt) {
                int arow = wr * 64 + mt * 16 + (m4 & 1) * 8 + ri;
                int acol = ks * 16 + (m4 >> 1) * 8;
                ldsm4(af[mt], sa + (uint32_t)(arow * SROWH + acol) * 2u);
            }
            #pragma unroll
            for (int np = 0; np < 2; ++np) {
                int brow = wc * 32 + np * 16 + (m4 >> 1) * 8 + ri;
                int bcol = ks * 16 + (m4 & 1) * 8;
                uint32_t t[4];
                ldsm4(t, sb + (uint32_t)(brow * SROWH + bcol) * 2u);
                bf[np * 2][0] = t[0]; bf[np * 2][1] = t[1];
                bf[np * 2 + 1][0] = t[2]; bf[np * 2 + 1][1] = t[3];
            }
            #pragma unroll
            for (int mt = 0; mt < 4; ++mt)
                #pragma unroll
                for (int nt = 0; nt < 4; ++nt)
                    mma_f16(c[mt][nt], af[mt], bf[nt]);
        }
    }

    #pragma unroll
    for (int mt = 0; mt < 4; ++mt) {
        #pragma unroll
        for (int nt = 0; nt < 4; ++nt) {
            int r   = row0 + wr * 64 + mt * 16 + g;
            int col = col0 + wc * 32 + nt * 8 + la3 * 2;
            float2 bv = *(const float2*)&bias[col];
            float v00 = c[mt][nt][0] + bv.x, v01 = c[mt][nt][1] + bv.y;
            float v10 = c[mt][nt][2] + bv.x, v11 = c[mt][nt][3] + bv.y;
            if (HOUT) {
                __half* C = (__half*)Cv;
                *(__half2*)&C[(size_t)r * N + col]       = __floats2half2_rn(v00, v01);
                *(__half2*)&C[(size_t)(r + 8) * N + col] = __floats2half2_rn(v10, v11);
            } else {
                float* C = (float*)Cv;
                *(float2*)&C[(size_t)r * N + col]       = make_float2(v00, v01);
                *(float2*)&C[(size_t)(r + 8) * N + col] = make_float2(v10, v11);
            }
        }
    }
}

// ---------------------------------------------------------------------------
// Prep: f32 -> f16 convert; transpose + convert
// ---------------------------------------------------------------------------
__global__ __launch_bounds__(256) void cvt_half4(
    const float* __restrict__ in, __half* __restrict__ out)
{
    int i = (blockIdx.x * 256 + threadIdx.x) * 4;
    float4 v = *(const float4*)&in[i];
    *(__half2*)&out[i]     = __floats2half2_rn(v.x, v.y);
    *(__half2*)&out[i + 2] = __floats2half2_rn(v.z, v.w);
}

__global__ __launch_bounds__(256) void transpose_h(
    const float* __restrict__ in, __half* __restrict__ out, int R, int Ccols)
{
    __shared__ float t[32][33];
    int r0 = blockIdx.y * 32, c0 = blockIdx.x * 32;
    #pragma unroll
    for (int i = threadIdx.y; i < 32; i += 8)
        t[i][threadIdx.x] = in[(size_t)(r0 + i) * Ccols + c0 + threadIdx.x];
    __syncthreads();
    #pragma unroll
    for (int i = threadIdx.y; i < 32; i += 8)
        out[(size_t)(c0 + i) * R + r0 + threadIdx.x] = __float2half_rn(t[threadIdx.x][i]);
}

// ---------------------------------------------------------------------------
// Flash attention (causal), fp16 mma + ldmatrix.
// 128 queries x (b,h); 8 warps x 16 rows; KV tiles of 64, 3-stage ring
// (prefetch 1 -> no WAR hazard). V frags via ldmatrix.trans (no transpose).
// P -> PV A-frag is pure register packing. Scale applied on S in f32.
// ---------------------------------------------------------------------------
#define AQ 128
#define AKV 64
#define ASTRH 72                                 // halves; 144B: conflict-free ldmatrix
#define SMQ_H 0
#define SMK_H (AQ * ASTRH)                       // 9216
#define SMV_H (SMK_H + 3 * AKV * ASTRH)          // 23040
#define ATTN_SMEM ((SMV_H + 3 * AKV * ASTRH) * 2)  // 73728 bytes

__global__ __launch_bounds__(256, 2) void attn_h(
    const __half* __restrict__ qkv, __half* __restrict__ y)
{
    extern __shared__ __half smh[];
    const uint32_t sb = smem_u32(smh);
    const int tid  = threadIdx.x;
    const int lane = tid & 31;
    const int w    = tid >> 5;
    const int g    = lane >> 2;
    const int la3  = lane & 3;
    const int m4   = lane >> 3;
    const int ri   = lane & 7;

    const int qblk = (gridDim.x - 1) - blockIdx.x;   // heavy blocks first
    const int q0   = qblk * AQ;
    const int h    = blockIdx.y;
    const int b    = blockIdx.z;
    const size_t base = (size_t)b * TSEQ * QKV_N + h * HDIM;

    // Stage Q (128 rows x 64 halves = 1024 chunks of 8h)
    #pragma unroll
    for (int it = 0; it < 4; ++it) {
        int idx = it * 256 + tid;
        int r = idx >> 3, ch = (idx & 7) * 8;
        CP_ASYNC16(sb + (uint32_t)(SMQ_H + r * ASTRH + ch) * 2u,
                   qkv + base + (size_t)(q0 + r) * QKV_N + ch);
    }

    const int ntile = q0 / AKV + 2;

    auto load_kv = [&](int t, int stage) {
        uint32_t ks_ = sb + (uint32_t)(SMK_H + stage * AKV * ASTRH) * 2u;
        uint32_t vs_ = sb + (uint32_t)(SMV_H + stage * AKV * ASTRH) * 2u;
        const __half* Kg = qkv + base + CDIM     + (size_t)t * AKV * QKV_N;
        const __half* Vg = qkv + base + 2 * CDIM + (size_t)t * AKV * QKV_N;
        #pragma unroll
        for (int it = 0; it < 2; ++it) {         // 64 rows x 8 chunks = 512
            int idx = it * 256 + tid;
            int r = idx >> 3, ch = (idx & 7) * 8;
            CP_ASYNC16(ks_ + (uint32_t)(r * ASTRH + ch) * 2u, Kg + (size_t)r * QKV_N + ch);
            CP_ASYNC16(vs_ + (uint32_t)(r * ASTRH + ch) * 2u, Vg + (size_t)r * QKV_N + ch);
        }
    };

    load_kv(0, 0);
    CP_COMMIT();
    CP_WAIT(0);
    __syncthreads();   // Q + KV(0) visible

    // Q fragments: 4 k-steps of 16 dims, one ldmatrix.x4 each
    uint32_t qf[4][4];
    #pragma unroll
    for (int ks = 0; ks < 4; ++ks) {
        int qrow = w * 16 + (m4 & 1) * 8 + ri;
        int qcol = ks * 16 + (m4 >> 1) * 8;
        ldsm4(qf[ks], sb + (uint32_t)(SMQ_H + qrow * ASTRH + qcol) * 2u);
    }

    float o[8][4];
    #pragma unroll
    for (int nt = 0; nt < 8; ++nt)
        #pragma unroll
        for (int q = 0; q < 4; ++q) o[nt][q] = 0.f;
    float m0 = -1e30f, m1 = -1e30f, l0 = 0.f, l1 = 0.f;

    const int row1 = q0 + w * 16 + g;
    const int row2 = row1 + 8;

    for (int t = 0; t < ntile; ++t) {
        if (t + 1 < ntile) load_kv(t + 1, (t + 1) % 3);
        CP_COMMIT();
        CP_WAIT(1);
        __syncthreads();   // KV(t) ready; ring-of-3 => no WAR hazard

        const int st = t % 3;
        const uint32_t ksb = sb + (uint32_t)(SMK_H + st * AKV * ASTRH) * 2u;
        const uint32_t vsb = sb + (uint32_t)(SMV_H + st * AKV * ASTRH) * 2u;

        // S = Q K^T   (B-frags: ldmatrix.x4 covers 2 key-tiles)
        float s[8][4];
        #pragma unroll
        for (int nt = 0; nt < 8; ++nt)
            #pragma unroll
            for (int q = 0; q < 4; ++q) s[nt][q] = 0.f;
        #pragma unroll
        for (int ks = 0; ks < 4; ++ks) {
            #pragma unroll
            for (int np = 0; np < 4; ++np) {
                int krow = np * 16 + (m4 >> 1) * 8 + ri;
                int kcol = ks * 16 + (m4 & 1) * 8;
                uint32_t tr[4];
                ldsm4(tr, ksb + (uint32_t)(krow * ASTRH + kcol) * 2u);
                uint32_t b0[2] = { tr[0], tr[1] };
                uint32_t b1[2] = { tr[2], tr[3] };
                mma_f16(s[np * 2],     qf[ks], b0);
                mma_f16(s[np * 2 + 1], qf[ks], b1);
            }
        }

        // scale (exact power of two) then causal mask
        #pragma unroll
        for (int nt = 0; nt < 8; ++nt) {
            s[nt][0] *= 0.125f; s[nt][1] *= 0.125f;
            s[nt][2] *= 0.125f; s[nt][3] *= 0.125f;
        }
        const int j0 = t * AKV;
        if (j0 >= q0) {
            #pragma unroll
            for (int nt = 0; nt < 8; ++nt) {
                int col = j0 + nt * 8 + 2 * la3;
                if (col     > row1) s[nt][0] = -1e30f;
                if (col + 1 > row1) s[nt][1] = -1e30f;
                if (col     > row2) s[nt][2] = -1e30f;
                if (col + 1 > row2) s[nt][3] = -1e30f;
            }
        }

        // row max
        float mx0 = -1e30f, mx1 = -1e30f;
        #pragma unroll
        for (int nt = 0; nt < 8; ++nt) {
            mx0 = fmaxf(mx0, fmaxf(s[nt][0], s[nt][1]));
            mx1 = fmaxf(mx1, fmaxf(s[nt][2], s[nt][3]));
        }
        mx0 = fmaxf(mx0, __shfl_xor_sync(0xffffffffu, mx0, 1));
        mx0 = fmaxf(mx0, __shfl_xor_sync(0xffffffffu, mx0, 2));
        mx1 = fmaxf(mx1, __shfl_xor_sync(0xffffffffu, mx1, 1));
        mx1 = fmaxf(mx1, __shfl_xor_sync(0xffffffffu, mx1, 2));

        float M0 = fmaxf(m0, mx0), M1 = fmaxf(m1, mx1);
        float corr0 = __expf(m0 - M0), corr1 = __expf(m1 - M1);
        m0 = M0; m1 = M1;
        #pragma unroll
        for (int nt = 0; nt < 8; ++nt) {
            o[nt][0] *= corr0; o[nt][1] *= corr0;
            o[nt][2] *= corr1; o[nt][3] *= corr1;
        }

        // P = exp(S - M), pack to fp16 A-frags (pure register packing)
        uint32_t pf[4][4];
        float ps0 = 0.f, ps1 = 0.f;
        #pragma unroll
        for (int j = 0; j < 4; ++j) {
            __half2 h00 = __floats2half2_rn(__expf(s[2*j][0]   - M0), __expf(s[2*j][1]   - M0));
            __half2 h01 = __floats2half2_rn(__expf(s[2*j][2]   - M1), __expf(s[2*j][3]   - M1));
            __half2 h10 = __floats2half2_rn(__expf(s[2*j+1][0] - M0), __expf(s[2*j+1][1] - M0));
            __half2 h11 = __floats2half2_rn(__expf(s[2*j+1][2] - M1), __expf(s[2*j+1][3] - M1));
            pf[j][0] = *(uint32_t*)&h00;   // (row g,   keys 16j+2la3,+1)
            pf[j][1] = *(uint32_t*)&h01;   // (row g+8, same)
            pf[j][2] = *(uint32_t*)&h10;   // (row g,   keys +8)
            pf[j][3] = *(uint32_t*)&h11;   // (row g+8, keys +8)
            float2 f00 = __half22float2(h00), f01 = __half22float2(h01);
            float2 f10 = __half22float2(h10), f11 = __half22float2(h11);
            ps0 += f00.x + f00.y + f10.x + f10.y;
            ps1 += f01.x + f01.y + f11.x + f11.y;
        }
        ps0 += __shfl_xor_sync(0xffffffffu, ps0, 1);
        ps0 += __shfl_xor_sync(0xffffffffu, ps0, 2);
        ps1 += __shfl_xor_sync(0xffffffffu, ps1, 1);
        ps1 += __shfl_xor_sync(0xffffffffu, ps1, 2);
        l0 = l0 * corr0 + ps0;
        l1 = l1 * corr1 + ps1;

        // O += P V   (B-frags via ldmatrix.trans on [key][dim] stage)
        #pragma unroll
        for (int j = 0; j < 4; ++j) {
            #pragma unroll
            for (int np = 0; np < 4; ++np) {
                int vrow = j * 16 + (m4 & 1) * 8 + ri;     // key
                int vcol = np * 16 + (m4 >> 1) * 8;        // dim
                uint32_t tr[4];
                ldsm4t(tr, vsb + (uint32_t)(vrow * ASTRH + vcol) * 2u);
                uint32_t b0[2] = { tr[0], tr[1] };
                uint32_t b1[2] = { tr[2], tr[3] };
                mma_f16(o[np * 2],     pf[j], b0);
                mma_f16(o[np * 2 + 1], pf[j], b1);
            }
        }
    }

    const float inv0 = 1.f / l0, inv1 = 1.f / l1;
    __half* y1 = &y[((size_t)b * TSEQ + row1) * CDIM + h * HDIM];
    __half* y2 = &y[((size_t)b * TSEQ + row2) * CDIM + h * HDIM];
    #pragma unroll
    for (int nt = 0; nt < 8; ++nt) {
        int col = nt * 8 + 2 * la3;
        *(__half2*)&y1[col] = __floats2half2_rn(o[nt][0] * inv0, o[nt][1] * inv0);
        *(__half2*)&y2[col] = __floats2half2_rn(o[nt][2] * inv1, o[nt][3] * inv1);
    }
}

// ---------------------------------------------------------------------------
extern "C" void kernel_launch(void* const* d_in, const int* in_sizes, int n_in,
                              void* d_out, int out_size)
{
    const float* x     = (const float*)d_in[0];
    const float* W_qkv = (const float*)d_in[1];
    const float* b_qkv = (const float*)d_in[2];
    const float* W_o   = (const float*)d_in[3];
    const float* b_o   = (const float*)d_in[4];
    float* out = (float*)d_out;

    __half *qkv_ptr, *yh_ptr, *xh_ptr, *wtq_ptr, *wto_ptr;
    cudaGetSymbolAddress((void**)&qkv_ptr, g_qkvh);
    cudaGetSymbolAddress((void**)&yh_ptr,  g_yh);
    cudaGetSymbolAddress((void**)&xh_ptr,  g_xh);
    cudaGetSymbolAddress((void**)&wtq_ptr, g_wtq);
    cudaGetSymbolAddress((void**)&wto_ptr, g_wto);

    cudaFuncSetAttribute(gemm_h<true>,  cudaFuncAttributeMaxDynamicSharedMemorySize, GEMM_SMEM);
    cudaFuncSetAttribute(gemm_h<false>, cudaFuncAttributeMaxDynamicSharedMemorySize, GEMM_SMEM);
    cudaFuncSetAttribute(attn_h, cudaFuncAttributeMaxDynamicSharedMemorySize, ATTN_SMEM);

    // Prep: convert x, transpose+convert weights
    cvt_half4<<<MROWS * CDIM / 1024, 256>>>(x, xh_ptr);
    transpose_h<<<dim3(QKV_N / 32, CDIM / 32), dim3(32, 8)>>>(W_qkv, wtq_ptr, CDIM, QKV_N);
    transpose_h<<<dim3(CDIM / 32, CDIM / 32), dim3(32, 8)>>>(W_o, wto_ptr, CDIM, CDIM);

    // qkv = half(x @ W_qkv + b_qkv)   [4096, 3072]
    gemm_h<true><<<dim3(QKV_N / BN, MROWS / BM), GTHREADS, GEMM_SMEM>>>(
        xh_ptr, wtq_ptr, b_qkv, qkv_ptr, MROWS, QKV_N, CDIM);

    // y = attention(qkv)  (half out)
    attn_h<<<dim3(TSEQ / AQ, NHEAD, BATCH), 256, ATTN_SMEM>>>(qkv_ptr, yh_ptr);

    // out = y @ W_o + b_o   [4096, 1024] fp32 out
    gemm_h<false><<<dim3(CDIM / BN, MROWS / BM), GTHREADS, GEMM_SMEM>>>(
        yh_ptr, wto_ptr, b_o, out, MROWS, CDIM, CDIM);
}

// round 10
// speedup vs baseline: 1.7692x; 1.6686x over previous
#include <cuda_runtime.h>
#include <cuda_fp16.h>
#include <math.h>
#include <cstdint>

#define BATCH 2
#define TSEQ  2048
#define CDIM  1024
#define NHEAD 16
#define HDIM  64
#define MROWS (BATCH*TSEQ)          // 4096
#define QKV_N (3*CDIM)              // 3072

// Scratch (no runtime allocation allowed)
__device__ __half g_qkvh[MROWS * QKV_N];    // [B*T, 3C] half
__device__ __half g_yh  [MROWS * CDIM];     // [B*T, C]  half (attn out)
__device__ __half g_xh  [MROWS * CDIM];     // half copy of x
__device__ __half g_wtq [QKV_N * CDIM];     // W_qkv^T half
__device__ __half g_wto [CDIM * CDIM];      // W_o^T   half

// ---------------------------------------------------------------------------
// helpers
// ---------------------------------------------------------------------------
__device__ __forceinline__ uint32_t smem_u32(const void* p) {
    uint32_t a;
    asm("{ .reg .u64 t; cvta.to.shared.u64 t, %1; cvt.u32.u64 %0, t; }" : "=r"(a) : "l"(p));
    return a;
}
#define CP_ASYNC16(dst, src) \
    asm volatile("cp.async.cg.shared.global [%0], [%1], 16;" :: "r"(dst), "l"(src) : "memory")
#define CP_COMMIT() asm volatile("cp.async.commit_group;" ::: "memory")
#define CP_WAIT(n)  asm volatile("cp.async.wait_group %0;" :: "n"(n) : "memory")

__device__ __forceinline__ void ldsm4(uint32_t* r, uint32_t a) {
    asm volatile("ldmatrix.sync.aligned.m8n8.x4.shared.b16 {%0,%1,%2,%3}, [%4];"
        : "=r"(r[0]), "=r"(r[1]), "=r"(r[2]), "=r"(r[3]) : "r"(a));
}
__device__ __forceinline__ void ldsm4t(uint32_t* r, uint32_t a) {
    asm volatile("ldmatrix.sync.aligned.m8n8.x4.trans.shared.b16 {%0,%1,%2,%3}, [%4];"
        : "=r"(r[0]), "=r"(r[1]), "=r"(r[2]), "=r"(r[3]) : "r"(a));
}
__device__ __forceinline__ void mma_f16(float* c, const uint32_t* a, const uint32_t* b) {
    asm volatile(
        "mma.sync.aligned.m16n8k16.row.col.f32.f16.f16.f32 "
        "{%0,%1,%2,%3}, {%4,%5,%6,%7}, {%8,%9}, {%0,%1,%2,%3};"
        : "+f"(c[0]), "+f"(c[1]), "+f"(c[2]), "+f"(c[3])
        : "r"(a[0]), "r"(a[1]), "r"(a[2]), "r"(a[3]), "r"(b[0]), "r"(b[1]));
}

// ---------------------------------------------------------------------------
// fp16 GEMM: C[M,N] = A[M,K] @ Bt[N,K]^T + bias[N]
// CTA 128x128, BK=64, 3-stage cp.async, 256 threads (8 warps, 2x4),
// warp tile 64x32. 2 CTAs/SM -> cross-CTA barrier-bubble overlap.
// 16 mainloop barriers (vs 32) per CTA.
// ---------------------------------------------------------------------------
#define BM 128
#define BN 128
#define BK 64
#define NST 3
#define SROWH 72                                 // halves; 144B: conflict-free ldmatrix
#define STAGE_H ((BM + BN) * SROWH)              // 18432 halves
#define GEMM_SMEM (NST * STAGE_H * 2)            // 110592 bytes
#define GTHREADS 256

template <bool HOUT>
__global__ __launch_bounds__(GTHREADS, 2) void gemm_h(
    const __half* __restrict__ A, const __half* __restrict__ Bt,
    const float* __restrict__ bias, void* __restrict__ Cv,
    int M, int N, int K)
{
    extern __shared__ __half smh[];
    const uint32_t sbase = smem_u32(smh);
    const int tid  = threadIdx.x;
    const int lane = tid & 31;
    const int w    = tid >> 5;
    const int wr   = w >> 2;       // 0..1 (row block of 64)
    const int wc   = w & 3;        // 0..3 (col block of 32)
    const int g    = lane >> 2;
    const int la3  = lane & 3;
    const int m4   = lane >> 3;    // ldmatrix matrix id
    const int ri   = lane & 7;     // ldmatrix row-in-matrix
    const int row0 = blockIdx.y * BM;
    const int col0 = blockIdx.x * BN;

    float c[4][4][4];
    #pragma unroll
    for (int i = 0; i < 4; ++i)
        #pragma unroll
        for (int j = 0; j < 4; ++j)
            #pragma unroll
            for (int q = 0; q < 4; ++q) c[i][j][q] = 0.f;

    const int nchunk = K / BK;

    auto load_stage = [&](int s, int kt) {
        uint32_t sa = sbase + (uint32_t)(s * STAGE_H) * 2u;
        uint32_t sb = sa + (uint32_t)(BM * SROWH) * 2u;
        const __half* Ab = A  + (size_t)row0 * K + kt * BK;
        const __half* Bb = Bt + (size_t)col0 * K + kt * BK;
        #pragma unroll
        for (int it = 0; it < 4; ++it) {     // A: 128 rows x 8 chunks of 8h
            int idx = it * GTHREADS + tid;
            int r = idx >> 3, ch = (idx & 7) * 8;
            CP_ASYNC16(sa + (uint32_t)(r * SROWH + ch) * 2u, Ab + (size_t)r * K + ch);
        }
        #pragma unroll
        for (int it = 0; it < 4; ++it) {     // B: 128 rows x 8 chunks
            int idx = it * GTHREADS + tid;
            int r = idx >> 3, ch = (idx & 7) * 8;
            CP_ASYNC16(sb + (uint32_t)(r * SROWH + ch) * 2u, Bb + (size_t)r * K + ch);
        }
    };

    load_stage(0, 0); CP_COMMIT();
    load_stage(1, 1); CP_COMMIT();

    for (int kt = 0; kt < nchunk; ++kt) {
        CP_WAIT(1);
        __syncthreads();
        if (kt + 2 < nchunk) load_stage((kt + 2) % NST, kt + 2);
        CP_COMMIT();

        uint32_t sa = sbase + (uint32_t)((kt % NST) * STAGE_H) * 2u;
        uint32_t sb = sa + (uint32_t)(BM * SROWH) * 2u;
        #pragma unroll
        for (int ks = 0; ks < 4; ++ks) {       // 4 k-steps of 16
            uint32_t af[4][4], bf[4][2];
            #pragma unroll
            for (int mt = 0; mt < 4; ++mt) {
                int arow = wr * 64 + mt * 16 + (m4 & 1) * 8 + ri;
                int acol = ks * 16 + (m4 >> 1) * 8;
                ldsm4(af[mt], sa + (uint32_t)(arow * SROWH + acol) * 2u);
            }
            #pragma unroll
            for (int np = 0; np < 2; ++np) {
                int brow = wc * 32 + np * 16 + (m4 >> 1) * 8 + ri;
                int bcol = ks * 16 + (m4 & 1) * 8;
                uint32_t t[4];
                ldsm4(t, sb + (uint32_t)(brow * SROWH + bcol) * 2u);
                bf[np * 2][0] = t[0]; bf[np * 2][1] = t[1];
                bf[np * 2 + 1][0] = t[2]; bf[np * 2 + 1][1] = t[3];
            }
            #pragma unroll
            for (int mt = 0; mt < 4; ++mt)
                #pragma unroll
                for (int nt = 0; nt < 4; ++nt)
                    mma_f16(c[mt][nt], af[mt], bf[nt]);
        }
    }

    #pragma unroll
    for (int mt = 0; mt < 4; ++mt) {
        #pragma unroll
        for (int nt = 0; nt < 4; ++nt) {
            int r   = row0 + wr * 64 + mt * 16 + g;
            int col = col0 + wc * 32 + nt * 8 + la3 * 2;
            float2 bv = *(const float2*)&bias[col];
            float v00 = c[mt][nt][0] + bv.x, v01 = c[mt][nt][1] + bv.y;
            float v10 = c[mt][nt][2] + bv.x, v11 = c[mt][nt][3] + bv.y;
            if (HOUT) {
                __half* C = (__half*)Cv;
                *(__half2*)&C[(size_t)r * N + col]       = __floats2half2_rn(v00, v01);
                *(__half2*)&C[(size_t)(r + 8) * N + col] = __floats2half2_rn(v10, v11);
            } else {
                float* C = (float*)Cv;
                *(float2*)&C[(size_t)r * N + col]       = make_float2(v00, v01);
                *(float2*)&C[(size_t)(r + 8) * N + col] = make_float2(v10, v11);
            }
        }
    }
}

// ---------------------------------------------------------------------------
// Prep: f32 -> f16 convert; transpose + convert
// ---------------------------------------------------------------------------
__global__ __launch_bounds__(256) void cvt_half4(
    const float* __restrict__ in, __half* __restrict__ out)
{
    int i = (blockIdx.x * 256 + threadIdx.x) * 4;
    float4 v = *(const float4*)&in[i];
    *(__half2*)&out[i]     = __floats2half2_rn(v.x, v.y);
    *(__half2*)&out[i + 2] = __floats2half2_rn(v.z, v.w);
}

__global__ __launch_bounds__(256) void transpose_h(
    const float* __restrict__ in, __half* __restrict__ out, int R, int Ccols)
{
    __shared__ float t[32][33];
    int r0 = blockIdx.y * 32, c0 = blockIdx.x * 32;
    #pragma unroll
    for (int i = threadIdx.y; i < 32; i += 8)
        t[i][threadIdx.x] = in[(size_t)(r0 + i) * Ccols + c0 + threadIdx.x];
    __syncthreads();
    #pragma unroll
    for (int i = threadIdx.y; i < 32; i += 8)
        out[(size_t)(c0 + i) * R + r0 + threadIdx.x] = __float2half_rn(t[threadIdx.x][i]);
}

// ---------------------------------------------------------------------------
// Flash attention (causal), fp16 mma + ldmatrix (unchanged from R9).
// ---------------------------------------------------------------------------
#define AQ 128
#define AKV 64
#define ASTRH 72
#define SMQ_H 0
#define SMK_H (AQ * ASTRH)                       // 9216
#define SMV_H (SMK_H + 3 * AKV * ASTRH)          // 23040
#define ATTN_SMEM ((SMV_H + 3 * AKV * ASTRH) * 2)  // 73728 bytes

__global__ __launch_bounds__(256, 2) void attn_h(
    const __half* __restrict__ qkv, __half* __restrict__ y)
{
    extern __shared__ __half smh[];
    const uint32_t sb = smem_u32(smh);
    const int tid  = threadIdx.x;
    const int lane = tid & 31;
    const int w    = tid >> 5;
    const int g    = lane >> 2;
    const int la3  = lane & 3;
    const int m4   = lane >> 3;
    const int ri   = lane & 7;

    const int qblk = (gridDim.x - 1) - blockIdx.x;   // heavy blocks first
    const int q0   = qblk * AQ;
    const int h    = blockIdx.y;
    const int b    = blockIdx.z;
    const size_t base = (size_t)b * TSEQ * QKV_N + h * HDIM;

    // Stage Q
    #pragma unroll
    for (int it = 0; it < 4; ++it) {
        int idx = it * 256 + tid;
        int r = idx >> 3, ch = (idx & 7) * 8;
        CP_ASYNC16(sb + (uint32_t)(SMQ_H + r * ASTRH + ch) * 2u,
                   qkv + base + (size_t)(q0 + r) * QKV_N + ch);
    }

    const int ntile = q0 / AKV + 2;

    auto load_kv = [&](int t, int stage) {
        uint32_t ks_ = sb + (uint32_t)(SMK_H + stage * AKV * ASTRH) * 2u;
        uint32_t vs_ = sb + (uint32_t)(SMV_H + stage * AKV * ASTRH) * 2u;
        const __half* Kg = qkv + base + CDIM     + (size_t)t * AKV * QKV_N;
        const __half* Vg = qkv + base + 2 * CDIM + (size_t)t * AKV * QKV_N;
        #pragma unroll
        for (int it = 0; it < 2; ++it) {
            int idx = it * 256 + tid;
            int r = idx >> 3, ch = (idx & 7) * 8;
            CP_ASYNC16(ks_ + (uint32_t)(r * ASTRH + ch) * 2u, Kg + (size_t)r * QKV_N + ch);
            CP_ASYNC16(vs_ + (uint32_t)(r * ASTRH + ch) * 2u, Vg + (size_t)r * QKV_N + ch);
        }
    };

    load_kv(0, 0);
    CP_COMMIT();
    CP_WAIT(0);
    __syncthreads();   // Q + KV(0) visible

    uint32_t qf[4][4];
    #pragma unroll
    for (int ks = 0; ks < 4; ++ks) {
        int qrow = w * 16 + (m4 & 1) * 8 + ri;
        int qcol = ks * 16 + (m4 >> 1) * 8;
        ldsm4(qf[ks], sb + (uint32_t)(SMQ_H + qrow * ASTRH + qcol) * 2u);
    }

    float o[8][4];
    #pragma unroll
    for (int nt = 0; nt < 8; ++nt)
        #pragma unroll
        for (int q = 0; q < 4; ++q) o[nt][q] = 0.f;
    float m0 = -1e30f, m1 = -1e30f, l0 = 0.f, l1 = 0.f;

    const int row1 = q0 + w * 16 + g;
    const int row2 = row1 + 8;

    for (int t = 0; t < ntile; ++t) {
        if (t + 1 < ntile) load_kv(t + 1, (t + 1) % 3);
        CP_COMMIT();
        CP_WAIT(1);
        __syncthreads();

        const int st = t % 3;
        const uint32_t ksb = sb + (uint32_t)(SMK_H + st * AKV * ASTRH) * 2u;
        const uint32_t vsb = sb + (uint32_t)(SMV_H + st * AKV * ASTRH) * 2u;

        // S = Q K^T
        float s[8][4];
        #pragma unroll
        for (int nt = 0; nt < 8; ++nt)
            #pragma unroll
            for (int q = 0; q < 4; ++q) s[nt][q] = 0.f;
        #pragma unroll
        for (int ks = 0; ks < 4; ++ks) {
            #pragma unroll
            for (int np = 0; np < 4; ++np) {
                int krow = np * 16 + (m4 >> 1) * 8 + ri;
                int kcol = ks * 16 + (m4 & 1) * 8;
                uint32_t tr[4];
                ldsm4(tr, ksb + (uint32_t)(krow * ASTRH + kcol) * 2u);
                uint32_t b0[2] = { tr[0], tr[1] };
                uint32_t b1[2] = { tr[2], tr[3] };
                mma_f16(s[np * 2],     qf[ks], b0);
                mma_f16(s[np * 2 + 1], qf[ks], b1);
            }
        }

        #pragma unroll
        for (int nt = 0; nt < 8; ++nt) {
            s[nt][0] *= 0.125f; s[nt][1] *= 0.125f;
            s[nt][2] *= 0.125f; s[nt][3] *= 0.125f;
        }
        const int j0 = t * AKV;
        if (j0 >= q0) {
            #pragma unroll
            for (int nt = 0; nt < 8; ++nt) {
                int col = j0 + nt * 8 + 2 * la3;
                if (col     > row1) s[nt][0] = -1e30f;
                if (col + 1 > row1) s[nt][1] = -1e30f;
                if (col     > row2) s[nt][2] = -1e30f;
                if (col + 1 > row2) s[nt][3] = -1e30f;
            }
        }

        float mx0 = -1e30f, mx1 = -1e30f;
        #pragma unroll
        for (int nt = 0; nt < 8; ++nt) {
            mx0 = fmaxf(mx0, fmaxf(s[nt][0], s[nt][1]));
            mx1 = fmaxf(mx1, fmaxf(s[nt][2], s[nt][3]));
        }
        mx0 = fmaxf(mx0, __shfl_xor_sync(0xffffffffu, mx0, 1));
        mx0 = fmaxf(mx0, __shfl_xor_sync(0xffffffffu, mx0, 2));
        mx1 = fmaxf(mx1, __shfl_xor_sync(0xffffffffu, mx1, 1));
        mx1 = fmaxf(mx1, __shfl_xor_sync(0xffffffffu, mx1, 2));

        float M0 = fmaxf(m0, mx0), M1 = fmaxf(m1, mx1);
        float corr0 = __expf(m0 - M0), corr1 = __expf(m1 - M1);
        m0 = M0; m1 = M1;
        #pragma unroll
        for (int nt = 0; nt < 8; ++nt) {
            o[nt][0] *= corr0; o[nt][1] *= corr0;
            o[nt][2] *= corr1; o[nt][3] *= corr1;
        }

        uint32_t pf[4][4];
        float ps0 = 0.f, ps1 = 0.f;
        #pragma unroll
        for (int j = 0; j < 4; ++j) {
            __half2 h00 = __floats2half2_rn(__expf(s[2*j][0]   - M0), __expf(s[2*j][1]   - M0));
            __half2 h01 = __floats2half2_rn(__expf(s[2*j][2]   - M1), __expf(s[2*j][3]   - M1));
            __half2 h10 = __floats2half2_rn(__expf(s[2*j+1][0] - M0), __expf(s[2*j+1][1] - M0));
            __half2 h11 = __floats2half2_rn(__expf(s[2*j+1][2] - M1), __expf(s[2*j+1][3] - M1));
            pf[j][0] = *(uint32_t*)&h00;
            pf[j][1] = *(uint32_t*)&h01;
            pf[j][2] = *(uint32_t*)&h10;
            pf[j][3] = *(uint32_t*)&h11;
            float2 f00 = __half22float2(h00), f01 = __half22float2(h01);
            float2 f10 = __half22float2(h10), f11 = __half22float2(h11);
            ps0 += f00.x + f00.y + f10.x + f10.y;
            ps1 += f01.x + f01.y + f11.x + f11.y;
        }
        ps0 += __shfl_xor_sync(0xffffffffu, ps0, 1);
        ps0 += __shfl_xor_sync(0xffffffffu, ps0, 2);
        ps1 += __shfl_xor_sync(0xffffffffu, ps1, 1);
        ps1 += __shfl_xor_sync(0xffffffffu, ps1, 2);
        l0 = l0 * corr0 + ps0;
        l1 = l1 * corr1 + ps1;

        // O += P V
        #pragma unroll
        for (int j = 0; j < 4; ++j) {
            #pragma unroll
            for (int np = 0; np < 4; ++np) {
                int vrow = j * 16 + (m4 & 1) * 8 + ri;
                int vcol = np * 16 + (m4 >> 1) * 8;
                uint32_t tr[4];
                ldsm4t(tr, vsb + (uint32_t)(vrow * ASTRH + vcol) * 2u);
                uint32_t b0[2] = { tr[0], tr[1] };
                uint32_t b1[2] = { tr[2], tr[3] };
                mma_f16(o[np * 2],     pf[j], b0);
                mma_f16(o[np * 2 + 1], pf[j], b1);
            }
        }
    }

    const float inv0 = 1.f / l0, inv1 = 1.f / l1;
    __half* y1 = &y[((size_t)b * TSEQ + row1) * CDIM + h * HDIM];
    __half* y2 = &y[((size_t)b * TSEQ + row2) * CDIM + h * HDIM];
    #pragma unroll
    for (int nt = 0; nt < 8; ++nt) {
        int col = nt * 8 + 2 * la3;
        *(__half2*)&y1[col] = __floats2half2_rn(o[nt][0] * inv0, o[nt][1] * inv0);
        *(__half2*)&y2[col] = __floats2half2_rn(o[nt][2] * inv1, o[nt][3] * inv1);
    }
}

// ---------------------------------------------------------------------------
extern "C" void kernel_launch(void* const* d_in, const int* in_sizes, int n_in,
                              void* d_out, int out_size)
{
    const float* x     = (const float*)d_in[0];
    const float* W_qkv = (const float*)d_in[1];
    const float* b_qkv = (const float*)d_in[2];
    const float* W_o   = (const float*)d_in[3];
    const float* b_o   = (const float*)d_in[4];
    float* out = (float*)d_out;

    __half *qkv_ptr, *yh_ptr, *xh_ptr, *wtq_ptr, *wto_ptr;
    cudaGetSymbolAddress((void**)&qkv_ptr, g_qkvh);
    cudaGetSymbolAddress((void**)&yh_ptr,  g_yh);
    cudaGetSymbolAddress((void**)&xh_ptr,  g_xh);
    cudaGetSymbolAddress((void**)&wtq_ptr, g_wtq);
    cudaGetSymbolAddress((void**)&wto_ptr, g_wto);

    cudaFuncSetAttribute(gemm_h<true>,  cudaFuncAttributeMaxDynamicSharedMemorySize, GEMM_SMEM);
    cudaFuncSetAttribute(gemm_h<false>, cudaFuncAttributeMaxDynamicSharedMemorySize, GEMM_SMEM);
    cudaFuncSetAttribute(attn_h, cudaFuncAttributeMaxDynamicSharedMemorySize, ATTN_SMEM);

    // Prep: convert x, transpose+convert weights
    cvt_half4<<<MROWS * CDIM / 1024, 256>>>(x, xh_ptr);
    transpose_h<<<dim3(QKV_N / 32, CDIM / 32), dim3(32, 8)>>>(W_qkv, wtq_ptr, CDIM, QKV_N);
    transpose_h<<<dim3(CDIM / 32, CDIM / 32), dim3(32, 8)>>>(W_o, wto_ptr, CDIM, CDIM);

    // qkv = half(x @ W_qkv + b_qkv)   [4096, 3072]
    gemm_h<true><<<dim3(QKV_N / BN, MROWS / BM), GTHREADS, GEMM_SMEM>>>(
        xh_ptr, wtq_ptr, b_qkv, qkv_ptr, MROWS, QKV_N, CDIM);

    // y = attention(qkv)  (half out)
    attn_h<<<dim3(TSEQ / AQ, NHEAD, BATCH), 256, ATTN_SMEM>>>(qkv_ptr, yh_ptr);

    // out = y @ W_o + b_o   [4096, 1024] fp32 out
    gemm_h<false><<<dim3(CDIM / BN, MROWS / BM), GTHREADS, GEMM_SMEM>>>(
        yh_ptr, wto_ptr, b_o, out, MROWS, CDIM, CDIM);
}